// round 2
// baseline (speedup 1.0000x reference)
#include <cuda_runtime.h>
#include <math.h>

#define DM   4096
#define LD   512
#define BB   4
#define SP   4096
#define STOT 4097
#define CHUNK 16
#define NCHUNK 257   /* ceil(4097/16) */

// -------------------- device scratch (no allocs allowed) --------------------
__device__ float g_Cq[BB * DM];
__device__ float g_Qc[BB * DM];
__device__ float g_Qr[BB * DM];
__device__ float g_u [BB * LD];
__device__ float g_t [BB * DM];                 // scale*(Wkr@Qr + Wdkv@u)
__device__ float g_m [BB * NCHUNK];
__device__ float g_l [BB * NCHUNK];
__device__ float g_acc[(size_t)BB * NCHUNK * DM];  // 16.8 MB flash partials
__device__ float g_wc[BB * NCHUNK];
__device__ float g_Linv[BB];
__device__ float g_p [BB * DM];
__device__ float g_a [BB * LD];
__device__ float g_av[BB * DM];

// -------------------- zero the atomic-accumulated buffers -------------------
__global__ void k_zero(float* __restrict__ out) {
    int i = blockIdx.x * blockDim.x + threadIdx.x;
    int stride = gridDim.x * blockDim.x;
    for (int j = i; j < BB * DM; j += stride) {
        g_Cq[j] = 0.f; g_Qc[j] = 0.f; g_Qr[j] = 0.f; g_av[j] = 0.f; out[j] = 0.f;
    }
    for (int j = i; j < BB * LD; j += stride) g_a[j] = 0.f;
}

// -------------------- y[b][j] += sum_d X[b][d] * W[d][j]  (split-K) ---------
__global__ __launch_bounds__(256) void k_gemv_n(
    const float* __restrict__ X, int xstride,
    const float* __restrict__ W, int ldw,
    float* __restrict__ Y, int ystride,
    int K, int N, int kchunk)
{
    __shared__ float sx[BB][256];
    int tid = threadIdx.x;
    int j = blockIdx.x * 256 + tid;
    int d0 = blockIdx.y * kchunk;
    int d1 = min(K, d0 + kchunk);
    float a0 = 0.f, a1 = 0.f, a2 = 0.f, a3 = 0.f;
    for (int db = d0; db < d1; db += 256) {
        int tile = min(256, d1 - db);
        if (tid < tile) {
            sx[0][tid] = X[0 * xstride + db + tid];
            sx[1][tid] = X[1 * xstride + db + tid];
            sx[2][tid] = X[2 * xstride + db + tid];
            sx[3][tid] = X[3 * xstride + db + tid];
        }
        __syncthreads();
        if (j < N) {
            const float* wp = W + (size_t)db * ldw + j;
            #pragma unroll 4
            for (int i = 0; i < tile; i++) {
                float w = __ldg(wp); wp += ldw;
                a0 += sx[0][i] * w; a1 += sx[1][i] * w;
                a2 += sx[2][i] * w; a3 += sx[3][i] * w;
            }
        }
        __syncthreads();
    }
    if (j < N) {
        atomicAdd(&Y[0 * ystride + j], a0);
        atomicAdd(&Y[1 * ystride + j], a1);
        atomicAdd(&Y[2 * ystride + j], a2);
        atomicAdd(&Y[3 * ystride + j], a3);
    }
}

// -------------------- y[b][r] = sum_c W[r][c] * X[b][c]  (warp per row) -----
__global__ __launch_bounds__(256) void k_gemv_t(
    const float* __restrict__ X, int xstride,
    const float* __restrict__ W, int ldw,
    float* __restrict__ Y, int ystride,
    int rows, int cols, int accum_scale, float scalev)
{
    int gw   = (blockIdx.x * blockDim.x + threadIdx.x) >> 5;
    int lane = threadIdx.x & 31;
    if (gw >= rows) return;
    const float* wp = W + (size_t)gw * ldw;
    float a0 = 0.f, a1 = 0.f, a2 = 0.f, a3 = 0.f;
    for (int c = lane; c < cols; c += 32) {
        float w = __ldg(wp + c);
        a0 += w * __ldg(&X[0 * xstride + c]);
        a1 += w * __ldg(&X[1 * xstride + c]);
        a2 += w * __ldg(&X[2 * xstride + c]);
        a3 += w * __ldg(&X[3 * xstride + c]);
    }
    #pragma unroll
    for (int o = 16; o > 0; o >>= 1) {
        a0 += __shfl_xor_sync(0xffffffffu, a0, o);
        a1 += __shfl_xor_sync(0xffffffffu, a1, o);
        a2 += __shfl_xor_sync(0xffffffffu, a2, o);
        a3 += __shfl_xor_sync(0xffffffffu, a3, o);
    }
    if (lane == 0) {
        if (accum_scale) {
            Y[0 * ystride + gw] = scalev * (Y[0 * ystride + gw] + a0);
            Y[1 * ystride + gw] = scalev * (Y[1 * ystride + gw] + a1);
            Y[2 * ystride + gw] = scalev * (Y[2 * ystride + gw] + a2);
            Y[3 * ystride + gw] = scalev * (Y[3 * ystride + gw] + a3);
        } else {
            Y[0 * ystride + gw] = a0;
            Y[1 * ystride + gw] = a1;
            Y[2 * ystride + gw] = a2;
            Y[3 * ystride + gw] = a3;
        }
    }
}

// -------------------- flash pass: score + online-softmax x-accumulation -----
__global__ __launch_bounds__(256) void k_flash(
    const float* __restrict__ x, const float* __restrict__ past)
{
    int b   = blockIdx.y;
    int c   = blockIdx.x;
    int tid = threadIdx.x;
    __shared__ float sred[8];
    __shared__ float sbroad;

    const float4* t4 = reinterpret_cast<const float4*>(g_t + (size_t)b * DM);
    float4 t0 = t4[tid], t1 = t4[tid + 256], t2 = t4[tid + 512], t3 = t4[tid + 768];

    float m = -INFINITY, l = 0.f;
    float4 A0 = {0,0,0,0}, A1 = {0,0,0,0}, A2 = {0,0,0,0}, A3 = {0,0,0,0};

    int s0 = c * CHUNK;
    for (int i = 0; i < CHUNK; i++) {
        int s = s0 + i;
        if (s >= STOT) break;
        const float* xp = (s < SP) ? (past + ((size_t)b * SP + s) * DM)
                                   : (x + (size_t)b * DM);
        const float4* xp4 = reinterpret_cast<const float4*>(xp);
        float4 v0 = xp4[tid], v1 = xp4[tid + 256], v2 = xp4[tid + 512], v3 = xp4[tid + 768];

        float p = v0.x*t0.x + v0.y*t0.y + v0.z*t0.z + v0.w*t0.w
                + v1.x*t1.x + v1.y*t1.y + v1.z*t1.z + v1.w*t1.w
                + v2.x*t2.x + v2.y*t2.y + v2.z*t2.z + v2.w*t2.w
                + v3.x*t3.x + v3.y*t3.y + v3.z*t3.z + v3.w*t3.w;

        #pragma unroll
        for (int o = 16; o > 0; o >>= 1) p += __shfl_xor_sync(0xffffffffu, p, o);
        if ((tid & 31) == 0) sred[tid >> 5] = p;
        __syncthreads();
        if (tid < 8) {
            float v = sred[tid];
            #pragma unroll
            for (int o = 4; o > 0; o >>= 1) v += __shfl_xor_sync(0xffu, v, o);
            if (tid == 0) sbroad = v;
        }
        __syncthreads();
        float score = sbroad;
        __syncthreads();

        float mn   = fmaxf(m, score);
        float corr = __expf(m - mn);
        float e    = __expf(score - mn);
        l = l * corr + e;
        A0.x = A0.x*corr + e*v0.x; A0.y = A0.y*corr + e*v0.y;
        A0.z = A0.z*corr + e*v0.z; A0.w = A0.w*corr + e*v0.w;
        A1.x = A1.x*corr + e*v1.x; A1.y = A1.y*corr + e*v1.y;
        A1.z = A1.z*corr + e*v1.z; A1.w = A1.w*corr + e*v1.w;
        A2.x = A2.x*corr + e*v2.x; A2.y = A2.y*corr + e*v2.y;
        A2.z = A2.z*corr + e*v2.z; A2.w = A2.w*corr + e*v2.w;
        A3.x = A3.x*corr + e*v3.x; A3.y = A3.y*corr + e*v3.y;
        A3.z = A3.z*corr + e*v3.z; A3.w = A3.w*corr + e*v3.w;
        m = mn;
    }

    float4* acc4 = reinterpret_cast<float4*>(g_acc + ((size_t)b * NCHUNK + c) * DM);
    acc4[tid] = A0; acc4[tid + 256] = A1; acc4[tid + 512] = A2; acc4[tid + 768] = A3;
    if (tid == 0) { g_m[b * NCHUNK + c] = m; g_l[b * NCHUNK + c] = l; }
}

// -------------------- per-batch softmax stats: M, exp weights, 1/L ----------
__global__ __launch_bounds__(256) void k_stats() {
    int b = blockIdx.x;
    int tid = threadIdx.x;
    __shared__ float sred[8];
    __shared__ float sM;

    float m = -INFINITY;
    for (int c = tid; c < NCHUNK; c += 256) m = fmaxf(m, g_m[b * NCHUNK + c]);
    #pragma unroll
    for (int o = 16; o > 0; o >>= 1) m = fmaxf(m, __shfl_xor_sync(0xffffffffu, m, o));
    if ((tid & 31) == 0) sred[tid >> 5] = m;
    __syncthreads();
    if (tid < 8) {
        float v = sred[tid];
        #pragma unroll
        for (int o = 4; o > 0; o >>= 1) v = fmaxf(v, __shfl_xor_sync(0xffu, v, o));
        if (tid == 0) sM = v;
    }
    __syncthreads();
    float M = sM;
    __syncthreads();

    float lsum = 0.f;
    for (int c = tid; c < NCHUNK; c += 256) {
        float w = __expf(g_m[b * NCHUNK + c] - M);
        g_wc[b * NCHUNK + c] = w;
        lsum += w * g_l[b * NCHUNK + c];
    }
    #pragma unroll
    for (int o = 16; o > 0; o >>= 1) lsum += __shfl_xor_sync(0xffffffffu, lsum, o);
    if ((tid & 31) == 0) sred[tid >> 5] = lsum;
    __syncthreads();
    if (tid == 0) {
        float L = 0.f;
        for (int w = 0; w < 8; w++) L += sred[w];
        g_Linv[b] = 1.f / L;
    }
}

// -------------------- combine chunk partials -> p[b][d] ---------------------
__global__ __launch_bounds__(256) void k_combine() {
    int b = blockIdx.y;
    int d = blockIdx.x * 256 + threadIdx.x;
    const float* accp = g_acc + (size_t)b * NCHUNK * DM + d;
    const float* wcp  = g_wc + b * NCHUNK;
    float s = 0.f;
    #pragma unroll 4
    for (int c = 0; c < NCHUNK; c++) s += wcp[c] * accp[(size_t)c * DM];
    g_p[b * DM + d] = s * g_Linv[b];
}

// ----------------------------------------------------------------------------
extern "C" void kernel_launch(void* const* d_in, const int* in_sizes, int n_in,
                              void* d_out, int out_size)
{
    const float* x    = (const float*)d_in[0];
    const float* past = (const float*)d_in[1];
    const float* Wdq  = (const float*)d_in[2];
    const float* Wuq  = (const float*)d_in[3];
    const float* Wqr  = (const float*)d_in[4];
    const float* Wdkv = (const float*)d_in[5];
    const float* Wkr  = (const float*)d_in[6];
    const float* F    = (const float*)d_in[7];   // [LD, 2*DM]
    const float* Wo   = (const float*)d_in[8];
    float* out = (float*)d_out;

    const float scale = 1.0f / sqrtf(2.0f * (float)DM);

    float *pCq, *pQc, *pQr, *pu, *pt, *pp, *pa, *pav;
    cudaGetSymbolAddress((void**)&pCq, g_Cq);
    cudaGetSymbolAddress((void**)&pQc, g_Qc);
    cudaGetSymbolAddress((void**)&pQr, g_Qr);
    cudaGetSymbolAddress((void**)&pu,  g_u);
    cudaGetSymbolAddress((void**)&pt,  g_t);
    cudaGetSymbolAddress((void**)&pp,  g_p);
    cudaGetSymbolAddress((void**)&pa,  g_a);
    cudaGetSymbolAddress((void**)&pav, g_av);

    // 1) zero atomic targets
    k_zero<<<128, 256>>>(out);

    // 2) Cq = x @ Wdq            [B,DM]
    k_gemv_n<<<dim3(16, 16), 256>>>(x, DM, Wdq, DM, pCq, DM, DM, DM, 256);
    // 3) Qc = Cq @ Wuq
    k_gemv_n<<<dim3(16, 16), 256>>>(pCq, DM, Wuq, DM, pQc, DM, DM, DM, 256);
    // 4) Qr = Cq @ Wqr
    k_gemv_n<<<dim3(16, 16), 256>>>(pCq, DM, Wqr, DM, pQr, DM, DM, DM, 256);
    // 5) t = Wkr @ Qr            (write)
    k_gemv_t<<<512, 256>>>(pQr, DM, Wkr, DM, pt, DM, DM, DM, 0, 0.f);
    // 6) u = F[:, :DM] @ Qc      (write)  rows=LD, cols=DM, ldw=2*DM
    k_gemv_t<<<64, 256>>>(pQc, DM, F, 2 * DM, pu, LD, LD, DM, 0, 0.f);
    // 7) t = scale * (t + Wdkv @ u)
    k_gemv_t<<<512, 256>>>(pu, LD, Wdkv, LD, pt, DM, DM, LD, 1, scale);

    // 8) flash pass over [past_x; x]
    k_flash<<<dim3(NCHUNK, BB), 256>>>(x, past);
    // 9) softmax stats
    k_stats<<<BB, 256>>>();
    // 10) combine -> p[b][d] = softmax-weighted sum of xcat rows
    k_combine<<<dim3(16, BB), 256>>>();

    // 11) a = p @ Wdkv           [B,LD]
    k_gemv_n<<<dim3(2, 16), 256>>>(pp, DM, Wdkv, LD, pa, LD, DM, LD, 256);
    // 12) attn_v = a @ F[:, DM:] [B,DM]
    k_gemv_n<<<dim3(16, 4), 256>>>(pa, LD, F + DM, 2 * DM, pav, DM, LD, DM, 128);
    // 13) out = attn_v @ Wo      [B,DM]
    k_gemv_n<<<dim3(16, 16), 256>>>(pav, DM, Wo, DM, out, DM, DM, DM, 256);
}

// round 4
// speedup vs baseline: 1.5768x; 1.5768x over previous
#include <cuda_runtime.h>
#include <math.h>

#define DM   4096
#define LD   512
#define BB   4
#define SP   4096
#define STOT 4097
#define CHUNK 16
#define NCHUNK 257   /* ceil(4097/16) */

// -------------------- device scratch (no allocs allowed) --------------------
__device__ float g_Cq[BB * DM];
__device__ float g_Qc[BB * DM];
__device__ float g_Qr[BB * DM];
__device__ float g_u [BB * LD];
__device__ float g_t [BB * DM];                 // scale*(Wkr@Qr + Wdkv@u)
__device__ float g_m [BB * NCHUNK];
__device__ float g_l [BB * NCHUNK];
__device__ float g_acc[(size_t)BB * NCHUNK * DM];  // 16.8 MB flash partials
__device__ float g_wc[BB * NCHUNK];
__device__ float g_Linv[BB];
__device__ float g_p [BB * DM];
__device__ float g_a [BB * LD];
__device__ float g_av[BB * DM];

// -------------------- zero the atomic-accumulated buffers -------------------
__global__ void k_zero(float* __restrict__ out) {
    int i = blockIdx.x * blockDim.x + threadIdx.x;
    int stride = gridDim.x * blockDim.x;
    for (int j = i; j < BB * DM; j += stride) {
        g_Cq[j] = 0.f; g_Qc[j] = 0.f; g_Qr[j] = 0.f; g_av[j] = 0.f; out[j] = 0.f;
    }
    for (int j = i; j < BB * LD; j += stride) g_a[j] = 0.f;
}

__device__ __forceinline__ void fma4(float4& acc, float s, const float4& v) {
    acc.x += s * v.x; acc.y += s * v.y; acc.z += s * v.z; acc.w += s * v.w;
}

// ---- Y[b][:] += X[b][:] @ W   (float4 columns, split-K, unroll-16 MLP) -----
// blockIdx.z selects (W0,Y0) or (W1,Y1) so two independent gemvs share a launch.
__global__ __launch_bounds__(256) void k_gemv4(
    const float* __restrict__ X, int xstride,
    const float* __restrict__ W0, const float* __restrict__ W1, int ldw,
    float* __restrict__ Y0, float* __restrict__ Y1, int ystride,
    int K, int N, int kchunk)
{
    const float* W = blockIdx.z ? W1 : W0;
    float*       Y = blockIdx.z ? Y1 : Y0;
    const int N4 = N >> 2;
    const int ldw4 = ldw >> 2;
    int tid = threadIdx.x;
    int j4  = blockIdx.x * blockDim.x + tid;
    int d0  = blockIdx.y * kchunk;
    int d1  = min(K, d0 + kchunk);
    int nk  = d1 - d0;

    __shared__ float sx[BB][64];   // kchunk <= 64
    for (int i = tid; i < BB * nk; i += blockDim.x) {
        int bb = i / nk, kk = i - bb * nk;
        sx[bb][kk] = X[bb * xstride + d0 + kk];
    }
    __syncthreads();
    if (j4 >= N4) return;

    const float4* W4 = reinterpret_cast<const float4*>(W);
    float4 a0 = {0,0,0,0}, a1 = a0, a2 = a0, a3 = a0;

    int k = 0;
    for (; k + 16 <= nk; k += 16) {
        float4 wv[16];
        #pragma unroll
        for (int i = 0; i < 16; i++)
            wv[i] = W4[(size_t)(d0 + k + i) * ldw4 + j4];
        #pragma unroll
        for (int i = 0; i < 16; i++) {
            fma4(a0, sx[0][k + i], wv[i]);
            fma4(a1, sx[1][k + i], wv[i]);
            fma4(a2, sx[2][k + i], wv[i]);
            fma4(a3, sx[3][k + i], wv[i]);
        }
    }
    for (; k < nk; k++) {
        float4 wv = W4[(size_t)(d0 + k) * ldw4 + j4];
        fma4(a0, sx[0][k], wv); fma4(a1, sx[1][k], wv);
        fma4(a2, sx[2][k], wv); fma4(a3, sx[3][k], wv);
    }

    int j = j4 * 4;
    atomicAdd(&Y[0 * ystride + j + 0], a0.x); atomicAdd(&Y[0 * ystride + j + 1], a0.y);
    atomicAdd(&Y[0 * ystride + j + 2], a0.z); atomicAdd(&Y[0 * ystride + j + 3], a0.w);
    atomicAdd(&Y[1 * ystride + j + 0], a1.x); atomicAdd(&Y[1 * ystride + j + 1], a1.y);
    atomicAdd(&Y[1 * ystride + j + 2], a1.z); atomicAdd(&Y[1 * ystride + j + 3], a1.w);
    atomicAdd(&Y[2 * ystride + j + 0], a2.x); atomicAdd(&Y[2 * ystride + j + 1], a2.y);
    atomicAdd(&Y[2 * ystride + j + 2], a2.z); atomicAdd(&Y[2 * ystride + j + 3], a2.w);
    atomicAdd(&Y[3 * ystride + j + 0], a3.x); atomicAdd(&Y[3 * ystride + j + 1], a3.y);
    atomicAdd(&Y[3 * ystride + j + 2], a3.z); atomicAdd(&Y[3 * ystride + j + 3], a3.w);
}

// ---- y[b][r] = sum_c W[r][c] * X[b][c]   (warp/row, float4, unroll-8) ------
__global__ __launch_bounds__(256) void k_gemv_t(
    const float* __restrict__ X, int xstride,
    const float* __restrict__ W, int ldw,
    float* __restrict__ Y, int ystride,
    int rows, int cols, int accum_scale, float scalev)
{
    int gw   = (blockIdx.x * blockDim.x + threadIdx.x) >> 5;
    int lane = threadIdx.x & 31;
    if (gw >= rows) return;
    const float4* wp = reinterpret_cast<const float4*>(W + (size_t)gw * ldw);
    const float4* X4 = reinterpret_cast<const float4*>(X);
    int cols4 = cols >> 2;
    int x4s   = xstride >> 2;

    float4 a0 = {0,0,0,0}, a1 = a0, a2 = a0, a3 = a0;
    int cb = 0;
    for (; cb + 256 <= cols4; cb += 256) {
        float4 wv[8];
        #pragma unroll
        for (int i = 0; i < 8; i++) wv[i] = __ldg(&wp[cb + lane + 32 * i]);
        #pragma unroll
        for (int i = 0; i < 8; i++) {
            int c4 = cb + lane + 32 * i;
            float4 xv0 = __ldg(&X4[0 * x4s + c4]);
            float4 xv1 = __ldg(&X4[1 * x4s + c4]);
            float4 xv2 = __ldg(&X4[2 * x4s + c4]);
            float4 xv3 = __ldg(&X4[3 * x4s + c4]);
            a0.x += wv[i].x * xv0.x; a0.y += wv[i].y * xv0.y; a0.z += wv[i].z * xv0.z; a0.w += wv[i].w * xv0.w;
            a1.x += wv[i].x * xv1.x; a1.y += wv[i].y * xv1.y; a1.z += wv[i].z * xv1.z; a1.w += wv[i].w * xv1.w;
            a2.x += wv[i].x * xv2.x; a2.y += wv[i].y * xv2.y; a2.z += wv[i].z * xv2.z; a2.w += wv[i].w * xv2.w;
            a3.x += wv[i].x * xv3.x; a3.y += wv[i].y * xv3.y; a3.z += wv[i].z * xv3.z; a3.w += wv[i].w * xv3.w;
        }
    }
    #pragma unroll 4
    for (int c4 = cb + lane; c4 < cols4; c4 += 32) {
        float4 wv = __ldg(&wp[c4]);
        float4 xv0 = __ldg(&X4[0 * x4s + c4]);
        float4 xv1 = __ldg(&X4[1 * x4s + c4]);
        float4 xv2 = __ldg(&X4[2 * x4s + c4]);
        float4 xv3 = __ldg(&X4[3 * x4s + c4]);
        a0.x += wv.x * xv0.x; a0.y += wv.y * xv0.y; a0.z += wv.z * xv0.z; a0.w += wv.w * xv0.w;
        a1.x += wv.x * xv1.x; a1.y += wv.y * xv1.y; a1.z += wv.z * xv1.z; a1.w += wv.w * xv1.w;
        a2.x += wv.x * xv2.x; a2.y += wv.y * xv2.y; a2.z += wv.z * xv2.z; a2.w += wv.w * xv2.w;
        a3.x += wv.x * xv3.x; a3.y += wv.y * xv3.y; a3.z += wv.z * xv3.z; a3.w += wv.w * xv3.w;
    }

    float s0 = a0.x + a0.y + a0.z + a0.w;
    float s1 = a1.x + a1.y + a1.z + a1.w;
    float s2 = a2.x + a2.y + a2.z + a2.w;
    float s3 = a3.x + a3.y + a3.z + a3.w;
    #pragma unroll
    for (int o = 16; o > 0; o >>= 1) {
        s0 += __shfl_xor_sync(0xffffffffu, s0, o);
        s1 += __shfl_xor_sync(0xffffffffu, s1, o);
        s2 += __shfl_xor_sync(0xffffffffu, s2, o);
        s3 += __shfl_xor_sync(0xffffffffu, s3, o);
    }
    if (lane == 0) {
        if (accum_scale) {
            Y[0 * ystride + gw] = scalev * (Y[0 * ystride + gw] + s0);
            Y[1 * ystride + gw] = scalev * (Y[1 * ystride + gw] + s1);
            Y[2 * ystride + gw] = scalev * (Y[2 * ystride + gw] + s2);
            Y[3 * ystride + gw] = scalev * (Y[3 * ystride + gw] + s3);
        } else {
            Y[0 * ystride + gw] = s0;
            Y[1 * ystride + gw] = s1;
            Y[2 * ystride + gw] = s2;
            Y[3 * ystride + gw] = s3;
        }
    }
}

// ---- flash pass: score + online-softmax x-accumulation, pipelined ----------
__global__ __launch_bounds__(256) void k_flash(
    const float* __restrict__ x, const float* __restrict__ past)
{
    int b   = blockIdx.y;
    int c   = blockIdx.x;
    int tid = threadIdx.x;
    __shared__ float sred[2][8];

    const float4* t4 = reinterpret_cast<const float4*>(g_t + (size_t)b * DM);
    float4 t0 = t4[tid], t1 = t4[tid + 256], t2 = t4[tid + 512], t3 = t4[tid + 768];

    float m = -INFINITY, l = 0.f;
    float4 A0 = {0,0,0,0}, A1 = A0, A2 = A0, A3 = A0;

    int s0 = c * CHUNK;
    int nrows = min(CHUNK, STOT - s0);

    const float4* rp = reinterpret_cast<const float4*>(
        (s0 < SP) ? past + ((size_t)b * SP + s0) * DM : x + (size_t)b * DM);
    float4 v0 = rp[tid], v1 = rp[tid + 256], v2 = rp[tid + 512], v3 = rp[tid + 768];

    for (int i = 0; i < nrows; i++) {
        float p = v0.x*t0.x + v0.y*t0.y + v0.z*t0.z + v0.w*t0.w
                + v1.x*t1.x + v1.y*t1.y + v1.z*t1.z + v1.w*t1.w
                + v2.x*t2.x + v2.y*t2.y + v2.z*t2.z + v2.w*t2.w
                + v3.x*t3.x + v3.y*t3.y + v3.z*t3.z + v3.w*t3.w;

        // prefetch next row (loads stay outstanding across the barrier)
        float4 n0 = v0, n1 = v1, n2 = v2, n3 = v3;
        if (i + 1 < nrows) {
            int sn = s0 + i + 1;
            const float4* np = reinterpret_cast<const float4*>(
                (sn < SP) ? past + ((size_t)b * SP + sn) * DM : x + (size_t)b * DM);
            n0 = np[tid]; n1 = np[tid + 256]; n2 = np[tid + 512]; n3 = np[tid + 768];
        }

        #pragma unroll
        for (int o = 16; o > 0; o >>= 1) p += __shfl_xor_sync(0xffffffffu, p, o);
        if ((tid & 31) == 0) sred[i & 1][tid >> 5] = p;
        __syncthreads();
        float score = sred[i & 1][0] + sred[i & 1][1] + sred[i & 1][2] + sred[i & 1][3]
                    + sred[i & 1][4] + sred[i & 1][5] + sred[i & 1][6] + sred[i & 1][7];

        float mn   = fmaxf(m, score);
        float corr = __expf(m - mn);
        float e    = __expf(score - mn);
        l = l * corr + e;
        fma4(A0, corr - 1.f, A0); fma4(A0, e, v0);   // A0 = A0*corr + e*v0
        fma4(A1, corr - 1.f, A1); fma4(A1, e, v1);
        fma4(A2, corr - 1.f, A2); fma4(A2, e, v2);
        fma4(A3, corr - 1.f, A3); fma4(A3, e, v3);
        m = mn;
        v0 = n0; v1 = n1; v2 = n2; v3 = n3;
    }

    float4* acc4 = reinterpret_cast<float4*>(g_acc + ((size_t)b * NCHUNK + c) * DM);
    acc4[tid] = A0; acc4[tid + 256] = A1; acc4[tid + 512] = A2; acc4[tid + 768] = A3;
    if (tid == 0) { g_m[b * NCHUNK + c] = m; g_l[b * NCHUNK + c] = l; }
}

// -------------------- per-batch softmax stats: M, exp weights, 1/L ----------
__global__ __launch_bounds__(256) void k_stats() {
    int b = blockIdx.x;
    int tid = threadIdx.x;
    __shared__ float sred[8];
    __shared__ float sM;

    float m = -INFINITY;
    for (int c = tid; c < NCHUNK; c += 256) m = fmaxf(m, g_m[b * NCHUNK + c]);
    #pragma unroll
    for (int o = 16; o > 0; o >>= 1) m = fmaxf(m, __shfl_xor_sync(0xffffffffu, m, o));
    if ((tid & 31) == 0) sred[tid >> 5] = m;
    __syncthreads();
    if (tid < 8) {
        float v = sred[tid];
        #pragma unroll
        for (int o = 4; o > 0; o >>= 1) v = fmaxf(v, __shfl_xor_sync(0xffu, v, o));
        if (tid == 0) sM = v;
    }
    __syncthreads();
    float M = sM;
    __syncthreads();

    float lsum = 0.f;
    for (int c = tid; c < NCHUNK; c += 256) {
        float w = __expf(g_m[b * NCHUNK + c] - M);
        g_wc[b * NCHUNK + c] = w;
        lsum += w * g_l[b * NCHUNK + c];
    }
    #pragma unroll
    for (int o = 16; o > 0; o >>= 1) lsum += __shfl_xor_sync(0xffffffffu, lsum, o);
    if ((tid & 31) == 0) sred[tid >> 5] = lsum;
    __syncthreads();
    if (tid == 0) {
        float L = 0.f;
        for (int w = 0; w < 8; w++) L += sred[w];
        g_Linv[b] = 1.f / L;
    }
}

// -------------------- combine chunk partials -> p[b][d] ---------------------
__global__ __launch_bounds__(256) void k_combine() {
    int b = blockIdx.y;
    int d = blockIdx.x * 256 + threadIdx.x;
    const float* accp = g_acc + (size_t)b * NCHUNK * DM + d;
    const float* wcp  = g_wc + b * NCHUNK;
    float s = 0.f;
    #pragma unroll 4
    for (int c = 0; c < NCHUNK; c++) s += wcp[c] * accp[(size_t)c * DM];
    g_p[b * DM + d] = s * g_Linv[b];
}

// ----------------------------------------------------------------------------
extern "C" void kernel_launch(void* const* d_in, const int* in_sizes, int n_in,
                              void* d_out, int out_size)
{
    const float* x    = (const float*)d_in[0];
    const float* past = (const float*)d_in[1];
    const float* Wdq  = (const float*)d_in[2];
    const float* Wuq  = (const float*)d_in[3];
    const float* Wqr  = (const float*)d_in[4];
    const float* Wdkv = (const float*)d_in[5];
    const float* Wkr  = (const float*)d_in[6];
    const float* F    = (const float*)d_in[7];   // [LD, 2*DM]
    const float* Wo   = (const float*)d_in[8];
    float* out = (float*)d_out;

    const float scale = 1.0f / sqrtf(2.0f * (float)DM);

    float *pCq, *pQc, *pQr, *pu, *pt, *pp, *pa, *pav;
    cudaGetSymbolAddress((void**)&pCq, g_Cq);
    cudaGetSymbolAddress((void**)&pQc, g_Qc);
    cudaGetSymbolAddress((void**)&pQr, g_Qr);
    cudaGetSymbolAddress((void**)&pu,  g_u);
    cudaGetSymbolAddress((void**)&pt,  g_t);
    cudaGetSymbolAddress((void**)&pp,  g_p);
    cudaGetSymbolAddress((void**)&pa,  g_a);
    cudaGetSymbolAddress((void**)&pav, g_av);

    // 1) zero atomic targets
    k_zero<<<128, 256>>>(out);

    // 2) Cq = x @ Wdq                       [B,DM]  (64 MB)
    k_gemv4<<<dim3(4, 64, 1), 256>>>(x, DM, Wdq, Wdq, DM, pCq, pCq, DM, DM, DM, 64);
    // 3+4) Qc = Cq @ Wuq ; Qr = Cq @ Wqr    (merged, 128 MB)
    k_gemv4<<<dim3(4, 64, 2), 256>>>(pCq, DM, Wuq, Wqr, DM, pQc, pQr, DM, DM, DM, 64);
    // 5) t = Wkr @ Qr                       (64 MB)
    k_gemv_t<<<512, 256>>>(pQr, DM, Wkr, DM, pt, DM, DM, DM, 0, 0.f);
    // 6) u = F[:, :DM] @ Qc                 (8 MB)
    k_gemv_t<<<64, 256>>>(pQc, DM, F, 2 * DM, pu, LD, LD, DM, 0, 0.f);
    // 7) t = scale * (t + Wdkv @ u)         (8 MB)
    k_gemv_t<<<512, 256>>>(pu, LD, Wdkv, LD, pt, DM, DM, LD, 1, scale);

    // 8) flash pass over [past_x; x]        (268 MB)
    k_flash<<<dim3(NCHUNK, BB), 256>>>(x, past);
    // 9) softmax stats
    k_stats<<<BB, 256>>>();
    // 10) combine -> p[b][d]
    k_combine<<<dim3(16, BB), 256>>>();

    // 11) a = p @ Wdkv                      (8 MB)
    k_gemv4<<<dim3(1, 64, 1), 256>>>(pp, DM, Wdkv, Wdkv, LD, pa, pa, LD, DM, LD, 64);
    // 12) attn_v = a @ F[:, DM:]            (8 MB)
    k_gemv4<<<dim3(4, 8, 1), 256>>>(pa, LD, F + DM, F + DM, 2 * DM, pav, pav, DM, LD, DM, 64);
    // 13) out = attn_v @ Wo                 (64 MB)
    k_gemv4<<<dim3(4, 64, 1), 256>>>(pav, DM, Wo, Wo, DM, out, out, DM, DM, DM, 64);
}